// round 2
// baseline (speedup 1.0000x reference)
#include <cuda_runtime.h>

// NetG: encoder GRU (T=256) -> hidden += noise -> decoder GRU (T=256, shifted input) -> FC head.
// Persistent kernel, f32x2 packed FFMA, duplicated-pair weights in SMEM (one GRU resident,
// decoder weights reloaded at phase switch), per-batch-group grid barriers, h ping-pong in L2.

#define BSZ 512
#define TSZ 256
#define HSZ 256
#define NBLK 128
#define NTHR 256
#define BT 64   // batch tile per block
#define IT 16   // hidden tile per block

typedef unsigned long long u64;

__device__ float g_h[2][HSZ * BSZ];    // [buf][j * BSZ + b]
__device__ unsigned g_cnt[8 * 32];     // one counter per bblk group, 128B apart
__device__ unsigned g_genv[8 * 32];

__device__ __forceinline__ u64 pack2(float x) {
    u64 r; asm("mov.b64 %0, {%1, %1};" : "=l"(r) : "f"(x)); return r;
}
__device__ __forceinline__ float2 unpack2(u64 v) {
    float2 f; asm("mov.b64 {%0, %1}, %2;" : "=f"(f.x), "=f"(f.y) : "l"(v)); return f;
}
__device__ __forceinline__ void ffma2(u64 &d, u64 a, u64 b) {
    asm("fma.rn.f32x2 %0, %1, %2, %0;" : "+l"(d) : "l"(a), "l"(b));
}

__device__ __forceinline__ float sigf(float x) {
    return __fdividef(1.0f, 1.0f + __expf(-x));
}
__device__ __forceinline__ float tanhf_(float x) {
    return 1.0f - __fdividef(2.0f, __expf(2.0f * x) + 1.0f);
}

// 16-block group barrier (all blocks sharing a batch tile)
__device__ __forceinline__ void group_sync(int grp, unsigned &gen) {
    __syncthreads();
    if (threadIdx.x == 0) {
        unsigned* cnt = &g_cnt[grp * 32];
        unsigned* gv  = &g_genv[grp * 32];
        unsigned g = gen;
        __threadfence();
        if (atomicAdd(cnt, 1u) == 15u) {
            *cnt = 0;
            __threadfence();
            atomicExch(gv, g + 1);
        } else {
            while (*(volatile unsigned*)gv != g + 1) { }
        }
        __threadfence();
        gen = g + 1;
    }
    __syncthreads();
}

// stage one GRU's W_hh slice as duplicated pairs: w_s[(j*16+il)*8] = {r,r,z,z,n,n,0,0}
__device__ __forceinline__ void stage_whh(const float* __restrict__ W,
                                          float* __restrict__ w_s, int iblk, int tid) {
    #pragma unroll
    for (int k = 0; k < 48; ++k) {          // 16 il * 256 j * 3 g = 12288 elems / 256 thr
        int idx = tid + k * 256;
        int g = idx >> 12;                   // /4096
        int rem = idx & 4095;
        int i2 = rem >> 8;
        int j  = rem & 255;
        float w = W[(g * HSZ + iblk * IT + i2) * HSZ + j];
        *(float2*)(w_s + (j * 16 + i2) * 8 + g * 2) = make_float2(w, w);
    }
}

__device__ __forceinline__ void project_tile(
    const float* __restrict__ h_s, const float* __restrict__ wfc_s,
    float* __restrict__ out, int b0, int iblk, int tid, int tstep,
    float bf0, float bf1, float bf2)
{
    int bl = iblk * 4 + (tid >> 5);
    int lane = tid & 31;
    float a0 = 0.f, a1 = 0.f, a2 = 0.f;
    #pragma unroll
    for (int k = 0; k < 8; ++k) {
        int j = lane + k * 32;
        float hv = h_s[j * 68 + bl];
        a0 = fmaf(hv, wfc_s[j],       a0);
        a1 = fmaf(hv, wfc_s[256 + j], a1);
        a2 = fmaf(hv, wfc_s[512 + j], a2);
    }
    #pragma unroll
    for (int o = 16; o > 0; o >>= 1) {
        a0 += __shfl_xor_sync(0xffffffffu, a0, o);
        a1 += __shfl_xor_sync(0xffffffffu, a1, o);
        a2 += __shfl_xor_sync(0xffffffffu, a2, o);
    }
    if (lane == 0) {
        int base = ((b0 + bl) * TSZ + tstep) * 3;
        out[base + 0] = a0 + bf0;
        out[base + 1] = a1 + bf1;
        out[base + 2] = a2 + bf2;
    }
}

extern "C" __global__ void __launch_bounds__(NTHR, 1)
netg_kernel(const float* __restrict__ X_p, const float* __restrict__ X_f,
            const float* __restrict__ noise,
            const float* __restrict__ Wih_e, const float* __restrict__ Whh_e,
            const float* __restrict__ bih_e, const float* __restrict__ bhh_e,
            const float* __restrict__ Wih_d, const float* __restrict__ Whh_d,
            const float* __restrict__ bih_d, const float* __restrict__ bhh_d,
            const float* __restrict__ Wfc,   const float* __restrict__ bfc,
            float* __restrict__ out)
{
    extern __shared__ float smem[];
    float* h_s   = smem;                   // 256*68 floats, padded rows [j][b_local]
    float* w_s   = h_s + 256 * 68;         // 256*16*8 floats: [j][il]{r,r,z,z,n,n,0,0}
    float* wfc_s = w_s + 256 * 128;        // 768
    float* x_s   = wfc_s + 768;            // 64*3
    float4* h_s4 = (float4*)h_s;

    const int tid  = threadIdx.x;
    const int iblk = blockIdx.x & 15;
    const int bblk = blockIdx.x >> 4;
    const int b0   = bblk * BT;

    // warp-internal map: 8 bgrp x 4 il per warp -> h reads are 1 contiguous 128B wavefront
    const int lane = tid & 31;
    const int wrp  = tid >> 5;
    const int bgrp = (lane & 7) | ((wrp & 1) << 3);   // 0..15 (4 batches each)
    const int il   = (lane >> 3) | ((wrp >> 1) << 2); // 0..15
    const int ig   = iblk * IT + il;

    // ---- stage encoder recurrent weights + FC weights ----
    stage_whh(Whh_e, w_s, iblk, tid);
    for (int k = tid; k < 768; k += NTHR) wfc_s[k] = Wfc[k];

    // ---- per-thread input-gate params and biases, both phases ----
    float wE[9], wD[9], biE[3], biD[3];
    u64 bhE2[3], bhD2[3];
    #pragma unroll
    for (int g = 0; g < 3; ++g) {
        int row = g * HSZ + ig;
        biE[g] = bih_e[row]; bhE2[g] = pack2(bhh_e[row]);
        biD[g] = bih_d[row]; bhD2[g] = pack2(bhh_d[row]);
        #pragma unroll
        for (int d = 0; d < 3; ++d) {
            wE[g * 3 + d] = Wih_e[row * 3 + d];
            wD[g * 3 + d] = Wih_d[row * 3 + d];
        }
    }
    const float bf0 = bfc[0], bf1 = bfc[1], bf2 = bfc[2];

    // ---- zero h buffer 0 (encoder h0 = 0) ----
    {
        float* z = &g_h[0][blockIdx.x * 1024];
        z[tid] = 0.f; z[tid + 256] = 0.f; z[tid + 512] = 0.f; z[tid + 768] = 0.f;
    }

    unsigned gen = *(volatile unsigned*)&g_genv[bblk * 32];
    group_sync(bblk, gen);

    int cur = 0;
    for (int t = 0; t < 2 * TSZ; ++t) {
        const bool enc = (t < TSZ);
        const int tt = enc ? t : t - TSZ;

        // phase switch: reload recurrent weights for the decoder (once)
        if (t == TSZ) stage_whh(Whh_d, w_s, iblk, tid);

        // stage x_t tile (decoder input is right-shifted X_f; step 0 -> zeros)
        if (tid < 192) {
            int bl = tid / 3, d = tid - bl * 3;
            float v = 0.f;
            if (enc)          v = X_p[(b0 + bl) * (TSZ * 3) + tt * 3 + d];
            else if (tt > 0)  v = X_f[(b0 + bl) * (TSZ * 3) + (tt - 1) * 3 + d];
            x_s[bl * 3 + d] = v;
        }
        // stage h tile: g_h[cur][j][b0..b0+63] -> h_s (padded rows of 68 floats)
        {
            const float4* src = (const float4*)&g_h[cur][0];
            const int cofs = b0 >> 2;
            #pragma unroll
            for (int k = 0; k < 16; ++k) {
                int idx = tid + k * 256;
                int j = idx >> 4, b4 = idx & 15;
                h_s4[j * 17 + b4] = src[j * (BSZ / 4) + cofs + b4];
            }
        }
        __syncthreads();

        // fused output head: project Y_{tt-1} (== current h_s) during decoder steps
        if (!enc && tt >= 1 && tid < 128)
            project_tile(h_s, wfc_s, out, b0, iblk, tid, tt - 1, bf0, bf1, bf2);

        // phase params
        u64 aR0 = enc ? bhE2[0] : bhD2[0];
        u64 aZ0 = enc ? bhE2[1] : bhD2[1];
        u64 aN0 = enc ? bhE2[2] : bhD2[2];
        u64 aR1 = aR0, aZ1 = aZ0, aN1 = aN0;
        float wi[9], bi3[3];
        #pragma unroll
        for (int q = 0; q < 9; ++q) wi[q] = enc ? wE[q] : wD[q];
        #pragma unroll
        for (int q = 0; q < 3; ++q) bi3[q] = enc ? biE[q] : biD[q];

        // GEMM: gh[g][b] = b_hh[g] + sum_j h[b,j] * W_hh[g,j]  (f32x2: batch pairs)
        const float* hrow = h_s + bgrp * 4;
        const float* wrow = w_s + il * 8;
        #pragma unroll 8
        for (int j = 0; j < HSZ; ++j) {
            const ulonglong2 hv  = *(const ulonglong2*)(hrow + j * 68);
            const ulonglong2 wrz = *(const ulonglong2*)(wrow + j * 128);
            const u64        wnn = *(const u64*)       (wrow + j * 128 + 4);
            ffma2(aR0, wrz.x, hv.x);
            ffma2(aR1, wrz.x, hv.y);
            ffma2(aZ0, wrz.y, hv.x);
            ffma2(aZ1, wrz.y, hv.y);
            ffma2(aN0, wnn,   hv.x);
            ffma2(aN1, wnn,   hv.y);
        }

        float2 r01 = unpack2(aR0), r23 = unpack2(aR1);
        float2 z01 = unpack2(aZ0), z23 = unpack2(aZ1);
        float2 n01 = unpack2(aN0), n23 = unpack2(aN1);
        float rp[4] = {r01.x, r01.y, r23.x, r23.y};
        float zp[4] = {z01.x, z01.y, z23.x, z23.y};
        float np[4] = {n01.x, n01.y, n23.x, n23.y};

        // gates + h update (PyTorch GRU: r,z,n; b_hh_n inside r*( ))
        const bool add_noise = enc && (tt == TSZ - 1);
        float hnew[4];
        #pragma unroll
        for (int b = 0; b < 4; ++b) {
            int bl = bgrp * 4 + b;
            float x0 = x_s[bl * 3 + 0], x1 = x_s[bl * 3 + 1], x2 = x_s[bl * 3 + 2];
            float xr = bi3[0] + wi[0] * x0 + wi[1] * x1 + wi[2] * x2;
            float xz = bi3[1] + wi[3] * x0 + wi[4] * x1 + wi[5] * x2;
            float xn = bi3[2] + wi[6] * x0 + wi[7] * x1 + wi[8] * x2;
            float r = sigf(xr + rp[b]);
            float z = sigf(xz + zp[b]);
            float n = tanhf_(xn + r * np[b]);
            float hprev = h_s[ig * 68 + bl];
            float hn = n + z * (hprev - n);
            if (add_noise) hn += noise[(b0 + bl) * HSZ + ig];
            hnew[b] = hn;
        }
        *(float4*)&g_h[cur ^ 1][ig * BSZ + b0 + bgrp * 4] =
            make_float4(hnew[0], hnew[1], hnew[2], hnew[3]);

        cur ^= 1;
        group_sync(bblk, gen);
    }

    // epilogue: project the final decoder output Y_{T-1}
    {
        const float4* src = (const float4*)&g_h[cur][0];
        const int cofs = b0 >> 2;
        #pragma unroll
        for (int k = 0; k < 16; ++k) {
            int idx = tid + k * 256;
            int j = idx >> 4, b4 = idx & 15;
            h_s4[j * 17 + b4] = src[j * (BSZ / 4) + cofs + b4];
        }
        __syncthreads();
        if (tid < 128)
            project_tile(h_s, wfc_s, out, b0, iblk, tid, TSZ - 1, bf0, bf1, bf2);
    }
}

extern "C" void kernel_launch(void* const* d_in, const int* in_sizes, int n_in,
                              void* d_out, int out_size) {
    const float* X_p   = (const float*)d_in[0];
    const float* X_f   = (const float*)d_in[1];
    const float* noise = (const float*)d_in[2];
    const float* Wih_e = (const float*)d_in[3];
    const float* Whh_e = (const float*)d_in[4];
    const float* bih_e = (const float*)d_in[5];
    const float* bhh_e = (const float*)d_in[6];
    const float* Wih_d = (const float*)d_in[7];
    const float* Whh_d = (const float*)d_in[8];
    const float* bih_d = (const float*)d_in[9];
    const float* bhh_d = (const float*)d_in[10];
    const float* Wfc   = (const float*)d_in[11];
    const float* bfc   = (const float*)d_in[12];
    float* out = (float*)d_out;

    size_t smem_bytes = (size_t)(256 * 68 + 256 * 128 + 768 + 192) * sizeof(float);
    cudaFuncSetAttribute(netg_kernel, cudaFuncAttributeMaxDynamicSharedMemorySize,
                         (int)smem_bytes);

    netg_kernel<<<NBLK, NTHR, smem_bytes>>>(
        X_p, X_f, noise, Wih_e, Whh_e, bih_e, bhh_e,
        Wih_d, Whh_d, bih_d, bhh_d, Wfc, bfc, out);
}